// round 6
// baseline (speedup 1.0000x reference)
#include <cuda_runtime.h>

#define NB_VARS 2000000
#define M0 4000000
#define M1 1000000
#define M2 500000
#define M3 125000
#define E1 8000000
#define E3 1000000

// Scratch (allocation-free rule: __device__ globals)
__device__ float g_y0[M0];
__device__ float g_y1[M1];

// Fused input encoding: x = [0, 1, p0, 1-p0, p1, 1-p1, ...]
__device__ __forceinline__ float leaf_val(const float* __restrict__ xp, int idx) {
    if (idx >= 2) {
        float p = __ldg(xp + ((idx - 2) >> 1));
        return (idx & 1) ? (1.0f - p) : p;
    }
    return (float)idx;  // 0 -> 0.0, 1 -> 1.0
}

// Layer 0: 2 products per thread (4 gathers), float2 store. 2M threads.
// Also zeroes g_y1 and d_out (stream order guarantees completion before segsum1 / fused l2s3).
__global__ void __launch_bounds__(256) layer0_kernel(const float* __restrict__ xp,
                                                     const int4* __restrict__ ix,
                                                     float* __restrict__ out_zero) {
    int t = blockIdx.x * blockDim.x + threadIdx.x;     // [0, M0/2)
    if (t < M1 / 4) ((float4*)g_y1)[t] = make_float4(0.f, 0.f, 0.f, 0.f);
    if (t < M3 / 4) ((float4*)out_zero)[t] = make_float4(0.f, 0.f, 0.f, 0.f);
    if (t >= M0 / 2) return;
    int4 v = __ldg(ix + t);
    float2 r;
    r.x = leaf_val(xp, v.x) * leaf_val(xp, v.y);
    r.y = leaf_val(xp, v.z) * leaf_val(xp, v.w);
    ((float2*)g_y0)[t] = r;
}

// Segsum layer 1: 2 edges/thread (4M threads), scan-free local merge + REDG.
__global__ void __launch_bounds__(256) segsum1_kernel(const int2* __restrict__ ix_in,
                                                      const int2* __restrict__ ix_out) {
    int t = blockIdx.x * blockDim.x + threadIdx.x;     // [0, E1/2)
    if (t >= E1 / 2) return;
    int2 s = __ldg(ix_out + t);
    int2 g = __ldg(ix_in + t);
    float v0 = __ldg(g_y0 + g.x);
    float v1 = __ldg(g_y0 + g.y);
    if (s.x == s.y) {
        atomicAdd(g_y1 + s.x, v0 + v1);
    } else {
        atomicAdd(g_y1 + s.x, v0);
        atomicAdd(g_y1 + s.y, v1);
    }
}

// Fused layer2 + segsum3: 2 output-edges/thread (500K threads).
// Each edge e (from ix_in3) selects product e: y1[ix_in2[2e]] * y1[ix_in2[2e+1]].
__global__ void __launch_bounds__(256) l2s3_kernel(const int2* __restrict__ ix_in2,
                                                   const int2* __restrict__ ix_in3,
                                                   const int2* __restrict__ ix_out3,
                                                   float* __restrict__ out) {
    int t = blockIdx.x * blockDim.x + threadIdx.x;     // [0, E3/2)
    if (t >= E3 / 2) return;
    int2 e = __ldg(ix_in3 + t);
    int2 s = __ldg(ix_out3 + t);
    int2 p0 = __ldg(ix_in2 + e.x);
    int2 p1 = __ldg(ix_in2 + e.y);
    float a = __ldg(g_y1 + p0.x) * __ldg(g_y1 + p0.y);
    float b = __ldg(g_y1 + p1.x) * __ldg(g_y1 + p1.y);
    if (s.x == s.y) {
        atomicAdd(out + s.x, a + b);
    } else {
        atomicAdd(out + s.x, a);
        atomicAdd(out + s.y, b);
    }
}

extern "C" void kernel_launch(void* const* d_in, const int* in_sizes, int n_in,
                              void* d_out, int out_size) {
    const float* x_pos   = (const float*)d_in[0];
    const int*   ix_in0  = (const int*)d_in[1];
    const int*   ix_in1  = (const int*)d_in[2];
    const int*   ix_out1 = (const int*)d_in[3];
    const int*   ix_in2  = (const int*)d_in[4];
    const int*   ix_in3  = (const int*)d_in[5];
    const int*   ix_out3 = (const int*)d_in[6];
    float* out = (float*)d_out;

    const int B = 256;
    layer0_kernel <<<(M0 / 2 + B - 1) / B, B>>>(x_pos, (const int4*)ix_in0, out);
    segsum1_kernel<<<(E1 / 2 + B - 1) / B, B>>>((const int2*)ix_in1, (const int2*)ix_out1);
    l2s3_kernel   <<<(E3 / 2 + B - 1) / B, B>>>((const int2*)ix_in2, (const int2*)ix_in3,
                                                (const int2*)ix_out3, out);
}

// round 7
// speedup vs baseline: 1.0266x; 1.0266x over previous
#include <cuda_runtime.h>

#define NB_VARS 2000000
#define M0 4000000
#define M1 1000000
#define M2 500000
#define M3 125000
#define E1 8000000
#define E3 1000000

// Scratch (allocation-free rule: __device__ globals)
__device__ float g_y0[M0];
__device__ float g_y1[M1];

// Fused input encoding: x = [0, 1, p0, 1-p0, p1, 1-p1, ...]
__device__ __forceinline__ float leaf_val(const float* __restrict__ xp, int idx) {
    if (idx >= 2) {
        float p = __ldg(xp + ((idx - 2) >> 1));
        return (idx & 1) ? (1.0f - p) : p;
    }
    return (float)idx;  // 0 -> 0.0, 1 -> 1.0
}

// Layer 0: 4 products/thread (8 gathers in flight), float4 store. 1M threads.
// Also zeroes g_y1 and d_out (stream order guarantees completion before consumers).
__global__ void __launch_bounds__(256) layer0_kernel(const float* __restrict__ xp,
                                                     const int4* __restrict__ ix,
                                                     float* __restrict__ out_zero) {
    int t = blockIdx.x * blockDim.x + threadIdx.x;     // [0, M0/4)
    if (t < M1 / 4) ((float4*)g_y1)[t] = make_float4(0.f, 0.f, 0.f, 0.f);
    if (t < M3 / 4) ((float4*)out_zero)[t] = make_float4(0.f, 0.f, 0.f, 0.f);
    if (t >= M0 / 4) return;
    int4 a = __ldg(ix + 2 * t);
    int4 b = __ldg(ix + 2 * t + 1);
    float4 r;
    r.x = leaf_val(xp, a.x) * leaf_val(xp, a.y);
    r.y = leaf_val(xp, a.z) * leaf_val(xp, a.w);
    r.z = leaf_val(xp, b.x) * leaf_val(xp, b.y);
    r.w = leaf_val(xp, b.z) * leaf_val(xp, b.w);
    ((float4*)g_y0)[t] = r;
}

// Segsum layer 1: 4 edges/thread (2M threads), scan-free local run-merge + REDG.
// Runs spanning thread boundaries contribute via multiple atomics — still correct.
__global__ void __launch_bounds__(256) segsum1_kernel(const int4* __restrict__ ix_in,
                                                      const int4* __restrict__ ix_out) {
    int t = blockIdx.x * blockDim.x + threadIdx.x;     // [0, E1/4)
    if (t >= E1 / 4) return;
    int4 s = __ldg(ix_out + t);
    int4 g = __ldg(ix_in + t);
    // 4 independent gathers in flight
    float v0 = __ldg(g_y0 + g.x);
    float v1 = __ldg(g_y0 + g.y);
    float v2 = __ldg(g_y0 + g.z);
    float v3 = __ldg(g_y0 + g.w);
    float acc = v0;
    int cur = s.x;
    if (s.y == cur) acc += v1; else { atomicAdd(g_y1 + cur, acc); cur = s.y; acc = v1; }
    if (s.z == cur) acc += v2; else { atomicAdd(g_y1 + cur, acc); cur = s.z; acc = v2; }
    if (s.w == cur) acc += v3; else { atomicAdd(g_y1 + cur, acc); cur = s.w; acc = v3; }
    atomicAdd(g_y1 + cur, acc);
}

// Fused layer2 + segsum3: 2 output-edges/thread (500K threads, keeps concurrency).
// Edge e (from ix_in3) selects product e: y1[ix_in2[2e]] * y1[ix_in2[2e+1]].
__global__ void __launch_bounds__(256) l2s3_kernel(const int2* __restrict__ ix_in2,
                                                   const int2* __restrict__ ix_in3,
                                                   const int2* __restrict__ ix_out3,
                                                   float* __restrict__ out) {
    int t = blockIdx.x * blockDim.x + threadIdx.x;     // [0, E3/2)
    if (t >= E3 / 2) return;
    int2 e = __ldg(ix_in3 + t);
    int2 s = __ldg(ix_out3 + t);
    int2 p0 = __ldg(ix_in2 + e.x);
    int2 p1 = __ldg(ix_in2 + e.y);
    float a = __ldg(g_y1 + p0.x) * __ldg(g_y1 + p0.y);
    float b = __ldg(g_y1 + p1.x) * __ldg(g_y1 + p1.y);
    if (s.x == s.y) {
        atomicAdd(out + s.x, a + b);
    } else {
        atomicAdd(out + s.x, a);
        atomicAdd(out + s.y, b);
    }
}

extern "C" void kernel_launch(void* const* d_in, const int* in_sizes, int n_in,
                              void* d_out, int out_size) {
    const float* x_pos   = (const float*)d_in[0];
    const int*   ix_in0  = (const int*)d_in[1];
    const int*   ix_in1  = (const int*)d_in[2];
    const int*   ix_out1 = (const int*)d_in[3];
    const int*   ix_in2  = (const int*)d_in[4];
    const int*   ix_in3  = (const int*)d_in[5];
    const int*   ix_out3 = (const int*)d_in[6];
    float* out = (float*)d_out;

    const int B = 256;
    layer0_kernel <<<(M0 / 4 + B - 1) / B, B>>>(x_pos, (const int4*)ix_in0, out);
    segsum1_kernel<<<(E1 / 4 + B - 1) / B, B>>>((const int4*)ix_in1, (const int4*)ix_out1);
    l2s3_kernel   <<<(E3 / 2 + B - 1) / B, B>>>((const int2*)ix_in2, (const int2*)ix_in3,
                                                (const int2*)ix_out3, out);
}

// round 8
// speedup vs baseline: 1.0567x; 1.0293x over previous
#include <cuda_runtime.h>

#define NB_VARS 2000000
#define M0 4000000
#define M1 1000000
#define M2 500000
#define M3 125000
#define E1 8000000
#define E3 1000000

// Scratch (allocation-free rule: __device__ globals)
__device__ float g_y0[M0];
__device__ float g_y1[M1];
__device__ float g_y2[M2];

// Fused input encoding: x = [0, 1, p0, 1-p0, p1, 1-p1, ...]
__device__ __forceinline__ float leaf_val(const float* __restrict__ xp, int idx) {
    if (idx >= 2) {
        float p = __ldg(xp + ((idx - 2) >> 1));
        return (idx & 1) ? (1.0f - p) : p;
    }
    return (float)idx;  // 0 -> 0.0, 1 -> 1.0
}

// Layer 0: 2 products per thread (4 gathers), float2 store. 2M threads.
// Also zeroes g_y1 and d_out (stream order guarantees completion before consumers).
__global__ void __launch_bounds__(256) layer0_kernel(const float* __restrict__ xp,
                                                     const int4* __restrict__ ix,
                                                     float* __restrict__ out_zero) {
    int t = blockIdx.x * blockDim.x + threadIdx.x;     // [0, M0/2)
    if (t < M1 / 4) ((float4*)g_y1)[t] = make_float4(0.f, 0.f, 0.f, 0.f);
    if (t < M3 / 4) ((float4*)out_zero)[t] = make_float4(0.f, 0.f, 0.f, 0.f);
    if (t >= M0 / 2) return;
    int4 v = __ldg(ix + t);
    float2 r;
    r.x = leaf_val(xp, v.x) * leaf_val(xp, v.y);
    r.y = leaf_val(xp, v.z) * leaf_val(xp, v.w);
    ((float2*)g_y0)[t] = r;
}

// Segsum layer 1: 4 edges/thread (2M threads), scan-free local run-merge + REDG.
// Runs spanning thread boundaries contribute via multiple atomics — still correct.
__global__ void __launch_bounds__(256) segsum1_kernel(const int4* __restrict__ ix_in,
                                                      const int4* __restrict__ ix_out) {
    int t = blockIdx.x * blockDim.x + threadIdx.x;     // [0, E1/4)
    if (t >= E1 / 4) return;
    int4 s = __ldg(ix_out + t);
    int4 g = __ldg(ix_in + t);
    // 4 independent gathers in flight
    float v0 = __ldg(g_y0 + g.x);
    float v1 = __ldg(g_y0 + g.y);
    float v2 = __ldg(g_y0 + g.z);
    float v3 = __ldg(g_y0 + g.w);
    float acc = v0;
    int cur = s.x;
    if (s.y == cur) acc += v1; else { atomicAdd(g_y1 + cur, acc); cur = s.y; acc = v1; }
    if (s.z == cur) acc += v2; else { atomicAdd(g_y1 + cur, acc); cur = s.z; acc = v2; }
    if (s.w == cur) acc += v3; else { atomicAdd(g_y1 + cur, acc); cur = s.w; acc = v3; }
    atomicAdd(g_y1 + cur, acc);
}

// Layer 2: 2 products per thread over g_y1 -> g_y2. 250K threads.
__global__ void __launch_bounds__(256) layer2_kernel(const int4* __restrict__ ix) {
    int t = blockIdx.x * blockDim.x + threadIdx.x;     // [0, M2/2)
    if (t >= M2 / 2) return;
    int4 v = __ldg(ix + t);
    float2 r;
    r.x = __ldg(g_y1 + v.x) * __ldg(g_y1 + v.y);
    r.y = __ldg(g_y1 + v.z) * __ldg(g_y1 + v.w);
    ((float2*)g_y2)[t] = r;
}

// Segsum layer 3: 2 edges/thread (500K threads), scan-free pair merge + REDG.
__global__ void __launch_bounds__(256) segsum3_kernel(const int2* __restrict__ ix_in,
                                                      const int2* __restrict__ ix_out,
                                                      float* __restrict__ out) {
    int t = blockIdx.x * blockDim.x + threadIdx.x;     // [0, E3/2)
    if (t >= E3 / 2) return;
    int2 s = __ldg(ix_out + t);
    int2 g = __ldg(ix_in + t);
    float v0 = __ldg(g_y2 + g.x);
    float v1 = __ldg(g_y2 + g.y);
    if (s.x == s.y) {
        atomicAdd(out + s.x, v0 + v1);
    } else {
        atomicAdd(out + s.x, v0);
        atomicAdd(out + s.y, v1);
    }
}

extern "C" void kernel_launch(void* const* d_in, const int* in_sizes, int n_in,
                              void* d_out, int out_size) {
    const float* x_pos   = (const float*)d_in[0];
    const int*   ix_in0  = (const int*)d_in[1];
    const int*   ix_in1  = (const int*)d_in[2];
    const int*   ix_out1 = (const int*)d_in[3];
    const int*   ix_in2  = (const int*)d_in[4];
    const int*   ix_in3  = (const int*)d_in[5];
    const int*   ix_out3 = (const int*)d_in[6];
    float* out = (float*)d_out;

    const int B = 256;
    layer0_kernel <<<(M0 / 2 + B - 1) / B, B>>>(x_pos, (const int4*)ix_in0, out);
    segsum1_kernel<<<(E1 / 4 + B - 1) / B, B>>>((const int4*)ix_in1, (const int4*)ix_out1);
    layer2_kernel <<<(M2 / 2 + B - 1) / B, B>>>((const int4*)ix_in2);
    segsum3_kernel<<<(E3 / 2 + B - 1) / B, B>>>((const int2*)ix_in3, (const int2*)ix_out3, out);
}